// round 13
// baseline (speedup 1.0000x reference)
#include <cuda_runtime.h>
#include <cuda_bf16.h>
#include <cstdint>

#define NN   50000
#define EE   800000
#define HIDD 128
#define OUTD 4
#define NB   196        // ceil(NN/256) scan blocks

// ---------------- scratch (static device globals; no runtime allocation) ----
__device__ float g_hA[(size_t)NN * HIDD];
__device__ float g_hB[(size_t)NN * HIDD];
__device__ float g_L[NN];      // layer-1 attention scalars
__device__ float g_R[NN];
__device__ float g_L2[NN];     // layer-2 attention scalars (separate: no race)
__device__ float g_R2[NN];
__device__ int   g_cnt[NN];
__device__ int   g_cursor[NN];
__device__ int   g_start[NN + 1];
__device__ int   g_bsum[256];
__device__ int   g_csrc[EE];
__device__ float g_P[NN * OUTD];
__device__ float g_Q[NN * OUTD];
// bf16 3-term split operands
__device__ __nv_bfloat16 g_Ahi[(size_t)NN * HIDD];
__device__ __nv_bfloat16 g_Alo[(size_t)NN * HIDD];
__device__ __nv_bfloat16 g_Bh1[HIDD * HIDD];   // [n][k] = bf16_hi(W1[k][n])
__device__ __nv_bfloat16 g_Bl1[HIDD * HIDD];
__device__ __nv_bfloat16 g_Bh2[HIDD * HIDD];
__device__ __nv_bfloat16 g_Bl2[HIDD * HIDD];
// folded attention vectors: wl = W @ att_l, wr = W @ att_r
__device__ float g_wl1[HIDD], g_wr1[HIDD], g_wl2[HIDD], g_wr2[HIDD];

// ================= PTX helpers (sm_80+ baseline; compiles for sm_103) =======
__device__ __forceinline__ uint32_t smem_u32(const void* p) {
    uint32_t a;
    asm("{ .reg .u64 t; cvta.to.shared.u64 t, %1; cvt.u32.u64 %0, t; }"
        : "=r"(a) : "l"(p));
    return a;
}
__device__ __forceinline__ void cpa16(uint32_t saddr, const void* g, int nbytes) {
    asm volatile("cp.async.cg.shared.global [%0], [%1], 16, %2;"
                 :: "r"(saddr), "l"(g), "r"(nbytes) : "memory");
}
#define CPA_COMMIT() asm volatile("cp.async.commit_group;" ::: "memory")
#define CPA_WAIT1()  asm volatile("cp.async.wait_group 1;" ::: "memory")
#define CPA_WAIT0()  asm volatile("cp.async.wait_group 0;" ::: "memory")

__device__ __forceinline__ void ldsm4(uint32_t* r, uint32_t addr) {
    asm volatile("ldmatrix.sync.aligned.m8n8.x4.shared.b16 {%0,%1,%2,%3}, [%4];"
        : "=r"(r[0]), "=r"(r[1]), "=r"(r[2]), "=r"(r[3]) : "r"(addr));
}
__device__ __forceinline__ void mma16816(float* d, const uint32_t* a, const uint32_t* b) {
    asm volatile(
        "mma.sync.aligned.m16n8k16.row.col.f32.bf16.bf16.f32 "
        "{%0,%1,%2,%3}, {%4,%5,%6,%7}, {%8,%9}, {%0,%1,%2,%3};"
        : "+f"(d[0]), "+f"(d[1]), "+f"(d[2]), "+f"(d[3])
        : "r"(a[0]), "r"(a[1]), "r"(a[2]), "r"(a[3]), "r"(b[0]), "r"(b[1]));
}

// ---------------- wlr + zero: block 0 computes wl/wr; all blocks zero cnt ---
__global__ void wlr_zero_kernel(const float* __restrict__ W1, const float* __restrict__ al1,
                                const float* __restrict__ ar1,
                                const float* __restrict__ W2, const float* __restrict__ al2,
                                const float* __restrict__ ar2) {
    int i = blockIdx.x * blockDim.x + threadIdx.x;
    if (i < NN) { g_cnt[i] = 0; g_cursor[i] = 0; }
    if (blockIdx.x == 0 && threadIdx.x < HIDD) {
        int k = threadIdx.x;
        float l1 = 0.f, r1 = 0.f, l2 = 0.f, r2 = 0.f;
#pragma unroll 4
        for (int n = 0; n < HIDD; n++) {
            float w1 = W1[k * HIDD + n], w2 = W2[k * HIDD + n];
            l1 = fmaf(w1, al1[n], l1); r1 = fmaf(w1, ar1[n], r1);
            l2 = fmaf(w2, al2[n], l2); r2 = fmaf(w2, ar2[n], r2);
        }
        g_wl1[k] = l1; g_wr1[k] = r1; g_wl2[k] = l2; g_wr2[k] = r2;
    }
}

// ---------------- prep: split X; L1/R1; W^T splits; csr count ---------------
__global__ void prep_kernel(const float* __restrict__ X,
                            const float* __restrict__ W1,
                            const float* __restrict__ W2,
                            const int* __restrict__ ei) {
    int i = blockIdx.x * blockDim.x + threadIdx.x;
    if (i < NN * (HIDD / 4)) {
        int lane = i & 31;
        float4 v = ((const float4*)X)[i];
        __nv_bfloat16 h0 = __float2bfloat16(v.x), h1 = __float2bfloat16(v.y);
        __nv_bfloat16 h2 = __float2bfloat16(v.z), h3 = __float2bfloat16(v.w);
        __nv_bfloat162 hp0 = {h0, h1}, hp1 = {h2, h3};
        __nv_bfloat162 lp0 = {__float2bfloat16(v.x - __bfloat162float(h0)),
                              __float2bfloat16(v.y - __bfloat162float(h1))};
        __nv_bfloat162 lp1 = {__float2bfloat16(v.z - __bfloat162float(h2)),
                              __float2bfloat16(v.w - __bfloat162float(h3))};
        ((__nv_bfloat162*)g_Ahi)[i * 2]     = hp0;
        ((__nv_bfloat162*)g_Ahi)[i * 2 + 1] = hp1;
        ((__nv_bfloat162*)g_Alo)[i * 2]     = lp0;
        ((__nv_bfloat162*)g_Alo)[i * 2 + 1] = lp1;
        // fused L/R for layer 1 (warp == one row)
        float4 wl = *(const float4*)(g_wl1 + lane * 4);
        float4 wr = *(const float4*)(g_wr1 + lane * 4);
        float ls = v.x * wl.x + v.y * wl.y + v.z * wl.z + v.w * wl.w;
        float rs = v.x * wr.x + v.y * wr.y + v.z * wr.z + v.w * wr.w;
#pragma unroll
        for (int o = 16; o; o >>= 1) {
            ls += __shfl_xor_sync(0xFFFFFFFFu, ls, o);
            rs += __shfl_xor_sync(0xFFFFFFFFu, rs, o);
        }
        if (lane == 0) { g_L[i >> 5] = ls; g_R[i >> 5] = rs; }
    }
    if (i < HIDD * HIDD) {
        int k = i >> 7, n = i & 127;
        float w1 = W1[i], w2 = W2[i];
        __nv_bfloat16 h1 = __float2bfloat16(w1), h2 = __float2bfloat16(w2);
        g_Bh1[n * HIDD + k] = h1;
        g_Bl1[n * HIDD + k] = __float2bfloat16(w1 - __bfloat162float(h1));
        g_Bh2[n * HIDD + k] = h2;
        g_Bl2[n * HIDD + k] = __float2bfloat16(w2 - __bfloat162float(h2));
    }
    if (i < EE) atomicAdd(&g_cnt[ei[EE + i]], 1);   // fused CSR count
}

// ---------------- warp-MMA GEMM: H = X@W via 3-term bf16 split --------------
#define A_BYTES 10240   // 128 rows * 80B (32 bf16 + 8 pad)
#define B_BYTES 10240

__global__ __launch_bounds__(256) void gemm_mma_kernel(
        const __nv_bfloat16* __restrict__ Bhi, const __nv_bfloat16* __restrict__ Blo,
        float* __restrict__ H) {
    __shared__ __align__(16) __nv_bfloat16 As[2][128][40];
    __shared__ __align__(16) __nv_bfloat16 Bs[2][128][40];
    const int tid  = threadIdx.x;
    const int lane = tid & 31;
    const int wid  = tid >> 5;
    const int wm = (wid & 1) * 64;
    const int wn = (wid >> 1) * 32;
    const int row0 = blockIdx.x * 128;
    const uint32_t smA = smem_u32(&As[0][0][0]);
    const uint32_t smB = smem_u32(&Bs[0][0][0]);

    float acc[4][4][4];
#pragma unroll
    for (int mf = 0; mf < 4; mf++)
#pragma unroll
        for (int nf = 0; nf < 4; nf++)
#pragma unroll
            for (int j = 0; j < 4; j++) acc[mf][nf][j] = 0.f;

    auto prefetch = [&](int c) {
        const int term = c >> 2;
        const int kk = (c & 3) * 32;
        const int buf = c & 1;
        const __nv_bfloat16* Asrc = (term == 1) ? g_Alo : g_Ahi;
        const __nv_bfloat16* Bsrc = (term == 2) ? Blo : Bhi;
#pragma unroll
        for (int j = 0; j < 2; j++) {
            int vidx = tid * 2 + j;
            int row = vidx >> 2, q = vidx & 3;
            int grow = row0 + row;
            int ok = (grow < NN) ? 16 : 0;
            int gsafe = (grow < NN) ? grow : (NN - 1);
            cpa16(smA + buf * A_BYTES + row * 80 + q * 16,
                  Asrc + (size_t)gsafe * HIDD + kk + q * 8, ok);
            cpa16(smB + buf * B_BYTES + row * 80 + q * 16,
                  Bsrc + (size_t)row * HIDD + kk + q * 8, 16);
        }
        CPA_COMMIT();
    };

    prefetch(0);
    for (int c = 0; c < 12; c++) {
        if (c + 1 < 12) { prefetch(c + 1); CPA_WAIT1(); }
        else           { CPA_WAIT0(); }
        __syncthreads();
        const int buf = c & 1;
        uint32_t aAddr = smA + buf * A_BYTES + (wm + (lane & 15)) * 80 + (lane >> 4) * 16;
        uint32_t bAddr = smB + buf * B_BYTES + (wn + (lane & 15)) * 80 + (lane >> 4) * 16;
#pragma unroll
        for (int ks = 0; ks < 2; ks++) {
            uint32_t af[4][4], bfr[4][2], t0[4], t1[4];
#pragma unroll
            for (int mf = 0; mf < 4; mf++)
                ldsm4(af[mf], aAddr + mf * (16 * 80) + ks * 32);
            ldsm4(t0, bAddr + ks * 32);
            ldsm4(t1, bAddr + 16 * 80 + ks * 32);
            bfr[0][0] = t0[0]; bfr[0][1] = t0[2];
            bfr[1][0] = t0[1]; bfr[1][1] = t0[3];
            bfr[2][0] = t1[0]; bfr[2][1] = t1[2];
            bfr[3][0] = t1[1]; bfr[3][1] = t1[3];
#pragma unroll
            for (int mf = 0; mf < 4; mf++)
#pragma unroll
                for (int nf = 0; nf < 4; nf++)
                    mma16816(acc[mf][nf], af[mf], bfr[nf]);
        }
        __syncthreads();
    }

    const int g = lane >> 2, tq = lane & 3;
#pragma unroll
    for (int mf = 0; mf < 4; mf++) {
        int r_ = row0 + wm + mf * 16 + g;
#pragma unroll
        for (int nf = 0; nf < 4; nf++) {
            int cc = wn + nf * 8 + tq * 2;
            if (r_ < NN)
                *(float2*)(H + (size_t)r_ * HIDD + cc) = make_float2(acc[mf][nf][0], acc[mf][nf][1]);
            if (r_ + 8 < NN)
                *(float2*)(H + (size_t)(r_ + 8) * HIDD + cc) = make_float2(acc[mf][nf][2], acc[mf][nf][3]);
        }
    }
}

// ---------------- CSR scan (hierarchical) ------------------------------------
__global__ __launch_bounds__(256) void csr_scan1_kernel() {
    __shared__ int ws[8];
    const int tid = threadIdx.x, lane = tid & 31, wid = tid >> 5;
    const int i = blockIdx.x * 256 + tid;
    int v = (i < NN) ? g_cnt[i] : 0;
    int x = v;
#pragma unroll
    for (int o = 1; o < 32; o <<= 1) {
        int y = __shfl_up_sync(0xFFFFFFFFu, x, o);
        if (lane >= o) x += y;
    }
    if (lane == 31) ws[wid] = x;
    __syncthreads();
    if (tid < 8) {
        int s = ws[tid];
#pragma unroll
        for (int o = 1; o < 8; o <<= 1) {
            int y = __shfl_up_sync(0xFFu, s, o);
            if (tid >= o) s += y;
        }
        ws[tid] = s;
    }
    __syncthreads();
    int pre = (wid > 0 ? ws[wid - 1] : 0);
    if (i < NN) g_start[i] = pre + x - v;
    if (tid == 255) g_bsum[blockIdx.x] = pre + x;
}

__global__ __launch_bounds__(256) void csr_scan2_kernel() {
    __shared__ int ws[8];
    const int tid = threadIdx.x, lane = tid & 31, wid = tid >> 5;
    int v = (tid < NB) ? g_bsum[tid] : 0;
    int x = v;
#pragma unroll
    for (int o = 1; o < 32; o <<= 1) {
        int y = __shfl_up_sync(0xFFFFFFFFu, x, o);
        if (lane >= o) x += y;
    }
    if (lane == 31) ws[wid] = x;
    __syncthreads();
    if (tid < 8) {
        int s = ws[tid];
#pragma unroll
        for (int o = 1; o < 8; o <<= 1) {
            int y = __shfl_up_sync(0xFFu, s, o);
            if (tid >= o) s += y;
        }
        ws[tid] = s;
    }
    __syncthreads();
    int pre = (wid > 0 ? ws[wid - 1] : 0);
    if (tid < NB) g_bsum[tid] = pre + x - v;
}

__global__ void csr_scan3_kernel() {
    int i = blockIdx.x * blockDim.x + threadIdx.x;
    if (i < NN) g_start[i] += g_bsum[i >> 8];
    if (i == 0) g_start[NN] = EE;
}

__global__ void csr_scatter_kernel(const int* __restrict__ ei) {
    int e = blockIdx.x * blockDim.x + threadIdx.x;
    if (e >= EE) return;
    int s = ei[e], d = ei[EE + e];
    int pos = g_start[d] + atomicAdd(&g_cursor[d], 1);
    g_csrc[pos] = s;
}

// ============ fused attention mainloop (cp.async smem-staged pipeline) ======
// Per warp: 2-stage x 4-edge ring in shared memory. Each lane cp.asyncs its
// own 16B and reads back only its own bytes -> per-thread wait, no syncwarp.
#define ATTN_BODY(LARR)                                                        \
    float4 hd = ((const float4*)(H + (size_t)n * HIDD))[lane];                 \
    float dp = hd.x * hd.x + hd.y * hd.y + hd.z * hd.z + hd.w * hd.w;          \
    _Pragma("unroll")                                                          \
    for (int o = 16; o; o >>= 1) dp += __shfl_xor_sync(0xFFFFFFFFu, dp, o);    \
    float a0 = (Ln + Rd) * __frcp_rn(1.f + __expf(-dp));                       \
    float w0 = __expf(a0);                                                     \
    float den = w0;                                                            \
    float4 acc = make_float4(w0 * hd.x, w0 * hd.y, w0 * hd.z, w0 * hd.w);      \
    const int beg = g_start[n], end = g_start[n + 1];                          \
    float Lst[2][4];                                                           \
    int p = beg, nextp = beg, inflight = 0;                                    \
    if (nextp < end) {                                                         \
        int nb = end - nextp; if (nb > 4) nb = 4;                              \
        _Pragma("unroll")                                                      \
        for (int j = 0; j < 4; j++) {                                          \
            int s = g_csrc[nextp + (j < nb ? j : 0)];                          \
            Lst[0][j] = LARR[s];                                               \
            cpa16(smem_u32(&buf[0][j][lane]),                                  \
                  H + (size_t)s * HIDD + lane * 4, 16);                        \
        }                                                                      \
        CPA_COMMIT(); nextp += 4; inflight = 1;                                \
    }                                                                          \
    if (nextp < end) {                                                         \
        int nb = end - nextp; if (nb > 4) nb = 4;                              \
        _Pragma("unroll")                                                      \
        for (int j = 0; j < 4; j++) {                                          \
            int s = g_csrc[nextp + (j < nb ? j : 0)];                          \
            Lst[1][j] = LARR[s];                                               \
            cpa16(smem_u32(&buf[1][j][lane]),                                  \
                  H + (size_t)s * HIDD + lane * 4, 16);                        \
        }                                                                      \
        CPA_COMMIT(); nextp += 4; inflight = 2;                                \
    }                                                                          \
    int it = 0;                                                                \
    while (p < end) {                                                          \
        if (inflight == 2) { CPA_WAIT1(); } else { CPA_WAIT0(); }              \
        const int st = it & 1;                                                 \
        int nb = end - p; if (nb > 4) nb = 4;                                  \
        float4 cs[4]; float cL[4];                                             \
        _Pragma("unroll")                                                      \
        for (int j = 0; j < 4; j++) { cs[j] = buf[st][j][lane]; cL[j] = Lst[st][j]; } \
        inflight--;                                                            \
        if (nextp < end) {                                                     \
            int nb2 = end - nextp; if (nb2 > 4) nb2 = 4;                       \
            _Pragma("unroll")                                                  \
            for (int j = 0; j < 4; j++) {                                      \
                int s = g_csrc[nextp + (j < nb2 ? j : 0)];                     \
                Lst[st][j] = LARR[s];                                          \
                cpa16(smem_u32(&buf[st][j][lane]),                             \
                      H + (size_t)s * HIDD + lane * 4, 16);                    \
            }                                                                  \
            CPA_COMMIT(); nextp += 4; inflight++;                              \
        }                                                                      \
        float d4[4];                                                           \
        _Pragma("unroll")                                                      \
        for (int j = 0; j < 4; j++)                                            \
            d4[j] = cs[j].x * hd.x + cs[j].y * hd.y + cs[j].z * hd.z + cs[j].w * hd.w; \
        _Pragma("unroll")                                                      \
        for (int o = 16; o; o >>= 1)                                           \
            _Pragma("unroll")                                                  \
            for (int j = 0; j < 4; j++)                                        \
                d4[j] += __shfl_xor_sync(0xFFFFFFFFu, d4[j], o);               \
        _Pragma("unroll")                                                      \
        for (int j = 0; j < 4; j++) {                                          \
            if (j < nb) {                                                      \
                float a = (cL[j] + Rd) * __frcp_rn(1.f + __expf(-d4[j]));      \
                float w = __expf(a);                                           \
                den += w;                                                      \
                acc.x = fmaf(w, cs[j].x, acc.x);                               \
                acc.y = fmaf(w, cs[j].y, acc.y);                               \
                acc.z = fmaf(w, cs[j].z, acc.z);                               \
                acc.w = fmaf(w, cs[j].w, acc.w);                               \
            }                                                                  \
        }                                                                      \
        p += 4; it++;                                                          \
    }

// ---------------- fused attention (layer 2) ---------------------------------
__global__ __launch_bounds__(256) void attn_kernel(
        const float* __restrict__ H, const float* __restrict__ bias,
        const float* __restrict__ Lv, const float* __restrict__ Rv,
        float* __restrict__ out) {
    __shared__ float4 sbuf[8][2][4][32];   // 32 KB
    const int wib  = threadIdx.x >> 5;
    int n    = (blockIdx.x * blockDim.x + threadIdx.x) >> 5;
    int lane = threadIdx.x & 31;
    if (n >= NN) return;
    float4 (*buf)[4][32] = sbuf[wib];
    float Rd = Rv[n];
    float Ln = Lv[n];

    ATTN_BODY(Lv)

    float inv = 1.f / (den + 1e-16f);
    float4 b = ((const float4*)bias)[lane];
    float4 r;
    r.x = fmaf(acc.x, inv, b.x);
    r.y = fmaf(acc.y, inv, b.y);
    r.z = fmaf(acc.z, inv, b.z);
    r.w = fmaf(acc.w, inv, b.w);
    ((float4*)(out + (size_t)n * HIDD))[lane] = r;
}

// ---------------- fused attention (layer 1): epilogue writes bf16 split ----
__global__ __launch_bounds__(256) void attn_split_kernel(
        const float* __restrict__ H, const float* __restrict__ bias) {
    __shared__ float4 sbuf[8][2][4][32];   // 32 KB
    const int wib  = threadIdx.x >> 5;
    int n    = (blockIdx.x * blockDim.x + threadIdx.x) >> 5;
    int lane = threadIdx.x & 31;
    if (n >= NN) return;
    float4 (*buf)[4][32] = sbuf[wib];
    float Rd = g_R[n];
    float Ln = g_L[n];

    ATTN_BODY(g_L)

    float inv = 1.f / (den + 1e-16f);
    float4 b = ((const float4*)bias)[lane];
    float r0 = fmaxf(fmaf(acc.x, inv, b.x), 0.f);
    float r1 = fmaxf(fmaf(acc.y, inv, b.y), 0.f);
    float r2 = fmaxf(fmaf(acc.z, inv, b.z), 0.f);
    float r3 = fmaxf(fmaf(acc.w, inv, b.w), 0.f);

    // bf16 split write (replaces hB write + conv_x kernel)
    __nv_bfloat16 h0 = __float2bfloat16(r0), h1 = __float2bfloat16(r1);
    __nv_bfloat16 h2 = __float2bfloat16(r2), h3 = __float2bfloat16(r3);
    __nv_bfloat162 hp0 = {h0, h1}, hp1 = {h2, h3};
    __nv_bfloat162 lp0 = {__float2bfloat16(r0 - __bfloat162float(h0)),
                          __float2bfloat16(r1 - __bfloat162float(h1))};
    __nv_bfloat162 lp1 = {__float2bfloat16(r2 - __bfloat162float(h2)),
                          __float2bfloat16(r3 - __bfloat162float(h3))};
    ((__nv_bfloat162*)(g_Ahi + (size_t)n * HIDD))[lane * 2]     = hp0;
    ((__nv_bfloat162*)(g_Ahi + (size_t)n * HIDD))[lane * 2 + 1] = hp1;
    ((__nv_bfloat162*)(g_Alo + (size_t)n * HIDD))[lane * 2]     = lp0;
    ((__nv_bfloat162*)(g_Alo + (size_t)n * HIDD))[lane * 2 + 1] = lp1;

    // fused L2/R2 = h . (wl2, wr2) -> SEPARATE buffers (no race with g_L/g_R)
    float4 wl = *(const float4*)(g_wl2 + lane * 4);
    float4 wr = *(const float4*)(g_wr2 + lane * 4);
    float ls = r0 * wl.x + r1 * wl.y + r2 * wl.z + r3 * wl.w;
    float rs = r0 * wr.x + r1 * wr.y + r2 * wr.z + r3 * wr.w;
#pragma unroll
    for (int o = 16; o; o >>= 1) {
        ls += __shfl_xor_sync(0xFFFFFFFFu, ls, o);
        rs += __shfl_xor_sync(0xFFFFFFFFu, rs, o);
    }
    if (lane == 0) { g_L2[n] = ls; g_R2[n] = rs; }
}

// ---------------- classifier decomposition ----------------------------------
__global__ void node_pq_kernel(const float* __restrict__ H,
                               const float* __restrict__ Wc) {
    int lane  = threadIdx.x & 31;
    int warp  = (blockIdx.x * blockDim.x + threadIdx.x) >> 5;
    int nwarp = (gridDim.x * blockDim.x) >> 5;
    float wt[4][4], wb[4][4];
#pragma unroll
    for (int i = 0; i < 4; i++)
#pragma unroll
        for (int o = 0; o < 4; o++) {
            wt[i][o] = Wc[(lane * 4 + i) * OUTD + o];
            wb[i][o] = Wc[(HIDD + lane * 4 + i) * OUTD + o];
        }
    for (int n = warp; n < NN; n += nwarp) {
        float4 hv = ((const float4*)(H + (size_t)n * HIDD))[lane];
        float h4[4] = {hv.x, hv.y, hv.z, hv.w};
        float pv[4] = {0.f, 0.f, 0.f, 0.f}, qv[4] = {0.f, 0.f, 0.f, 0.f};
#pragma unroll
        for (int i = 0; i < 4; i++)
#pragma unroll
            for (int o = 0; o < 4; o++) {
                pv[o] = fmaf(h4[i], wt[i][o], pv[o]);
                qv[o] = fmaf(h4[i], wb[i][o], qv[o]);
            }
#pragma unroll
        for (int o = 0; o < 4; o++)
#pragma unroll
            for (int off = 16; off; off >>= 1) {
                pv[o] += __shfl_xor_sync(0xFFFFFFFFu, pv[o], off);
                qv[o] += __shfl_xor_sync(0xFFFFFFFFu, qv[o], off);
            }
        if (lane == 0) {
            *(float4*)(g_P + (size_t)n * OUTD) = make_float4(pv[0], pv[1], pv[2], pv[3]);
            *(float4*)(g_Q + (size_t)n * OUTD) = make_float4(qv[0], qv[1], qv[2], qv[3]);
        }
    }
}

__global__ void edge_out_kernel(const int* __restrict__ ei,
                                const float* __restrict__ bc,
                                float* __restrict__ out) {
    int e = blockIdx.x * blockDim.x + threadIdx.x;
    if (e >= EE) return;
    int r = ei[e], c = ei[EE + e];
    float4 p = *(const float4*)(g_P + (size_t)r * OUTD);
    float4 q = *(const float4*)(g_Q + (size_t)c * OUTD);
    float b0 = bc[0], b1 = bc[1], b2 = bc[2], b3 = bc[3];
    *(float4*)(out + (size_t)e * OUTD) =
        make_float4(p.x + q.x + b0, p.y + q.y + b1, p.z + q.z + b2, p.w + q.w + b3);
}

// ---------------- launcher ---------------------------------------------------
extern "C" void kernel_launch(void* const* d_in, const int* in_sizes, int n_in,
                              void* d_out, int out_size) {
    const float* x   = (const float*)d_in[0];
    const int*   ei  = (const int*)d_in[1];
    const float* W1  = (const float*)d_in[2];
    const float* al1 = (const float*)d_in[3];
    const float* ar1 = (const float*)d_in[4];
    const float* b1  = (const float*)d_in[5];
    const float* W2  = (const float*)d_in[6];
    const float* al2 = (const float*)d_in[7];
    const float* ar2 = (const float*)d_in[8];
    const float* b2  = (const float*)d_in[9];
    const float* Wc  = (const float*)d_in[10];
    const float* bc  = (const float*)d_in[11];
    float* out = (float*)d_out;

    float *hA, *hB, *L2, *R2;
    __nv_bfloat16 *bh1, *bl1, *bh2, *bl2;
    cudaGetSymbolAddress((void**)&hA, g_hA);
    cudaGetSymbolAddress((void**)&hB, g_hB);
    cudaGetSymbolAddress((void**)&L2, g_L2);
    cudaGetSymbolAddress((void**)&R2, g_R2);
    cudaGetSymbolAddress((void**)&bh1, g_Bh1);
    cudaGetSymbolAddress((void**)&bl1, g_Bl1);
    cudaGetSymbolAddress((void**)&bh2, g_Bh2);
    cudaGetSymbolAddress((void**)&bl2, g_Bl2);

    const int TB = 256;
    const int gGemm = (NN + 127) / 128;               // 391
    const int gEdge = (EE + TB - 1) / TB;             // 3125
    const int gAttn = (NN * 32 + TB - 1) / TB;        // 6250
    const int gConv = (NN * 32 + TB - 1) / TB;        // 6250

    // prep: zero+wlr, then split/L/R/W^T/count, then scan+scatter
    wlr_zero_kernel<<<NB, 256>>>(W1, al1, ar1, W2, al2, ar2);
    prep_kernel<<<gConv, TB>>>(x, W1, W2, ei);
    csr_scan1_kernel<<<NB, 256>>>();
    csr_scan2_kernel<<<1, 256>>>();
    csr_scan3_kernel<<<NB, 256>>>();
    csr_scatter_kernel<<<gEdge, TB>>>(ei);

    // ---- layer 1 (attn writes bf16 split + L2/R2 to separate buffers) ----
    gemm_mma_kernel<<<gGemm, TB>>>(bh1, bl1, hA);
    attn_split_kernel<<<gAttn, TB>>>(hA, b1);

    // ---- layer 2 ----
    gemm_mma_kernel<<<gGemm, TB>>>(bh2, bl2, hA);
    attn_kernel<<<gAttn, TB>>>(hA, b2, L2, R2, hB);

    // ---- edge classifier ----
    node_pq_kernel<<<1184, TB>>>(hB, Wc);
    edge_out_kernel<<<gEdge, TB>>>(ei, bc, out);
}

// round 14
// speedup vs baseline: 1.0323x; 1.0323x over previous
#include <cuda_runtime.h>
#include <cuda_bf16.h>
#include <cstdint>

#define NN   50000
#define EE   800000
#define HIDD 128
#define OUTD 4
#define NB   196        // ceil(NN/256) scan blocks

// ---------------- scratch (static device globals; no runtime allocation) ----
__device__ float g_hA[(size_t)NN * HIDD];
__device__ float g_hB[(size_t)NN * HIDD];
__device__ float g_L[NN];      // layer-1 attention scalars
__device__ float g_R[NN];
__device__ float g_L2[NN];     // layer-2 attention scalars (separate: no race)
__device__ float g_R2[NN];
__device__ int   g_cnt[NN];
__device__ int   g_ord[EE];    // within-destination ordinal (from count atomic)
__device__ int   g_start[NN + 1];
__device__ int   g_bsum[256];
__device__ int   g_csrc[EE];
__device__ float g_P[NN * OUTD];
__device__ float g_Q[NN * OUTD];
// bf16 3-term split operands
__device__ __nv_bfloat16 g_Ahi[(size_t)NN * HIDD];
__device__ __nv_bfloat16 g_Alo[(size_t)NN * HIDD];
__device__ __nv_bfloat16 g_Bh1[HIDD * HIDD];   // [n][k] = bf16_hi(W1[k][n])
__device__ __nv_bfloat16 g_Bl1[HIDD * HIDD];
__device__ __nv_bfloat16 g_Bh2[HIDD * HIDD];
__device__ __nv_bfloat16 g_Bl2[HIDD * HIDD];
// folded attention vectors: wl = W @ att_l, wr = W @ att_r
__device__ float g_wl1[HIDD], g_wr1[HIDD], g_wl2[HIDD], g_wr2[HIDD];

// ================= PTX helpers (sm_80+ baseline; compiles for sm_103) =======
__device__ __forceinline__ uint32_t smem_u32(const void* p) {
    uint32_t a;
    asm("{ .reg .u64 t; cvta.to.shared.u64 t, %1; cvt.u32.u64 %0, t; }"
        : "=r"(a) : "l"(p));
    return a;
}
__device__ __forceinline__ void cpa16(uint32_t saddr, const void* g, int nbytes) {
    asm volatile("cp.async.cg.shared.global [%0], [%1], 16, %2;"
                 :: "r"(saddr), "l"(g), "r"(nbytes) : "memory");
}
#define CPA_COMMIT() asm volatile("cp.async.commit_group;" ::: "memory")
#define CPA_WAIT1()  asm volatile("cp.async.wait_group 1;" ::: "memory")
#define CPA_WAIT0()  asm volatile("cp.async.wait_group 0;" ::: "memory")

__device__ __forceinline__ void ldsm4(uint32_t* r, uint32_t addr) {
    asm volatile("ldmatrix.sync.aligned.m8n8.x4.shared.b16 {%0,%1,%2,%3}, [%4];"
        : "=r"(r[0]), "=r"(r[1]), "=r"(r[2]), "=r"(r[3]) : "r"(addr));
}
__device__ __forceinline__ void mma16816(float* d, const uint32_t* a, const uint32_t* b) {
    asm volatile(
        "mma.sync.aligned.m16n8k16.row.col.f32.bf16.bf16.f32 "
        "{%0,%1,%2,%3}, {%4,%5,%6,%7}, {%8,%9}, {%0,%1,%2,%3};"
        : "+f"(d[0]), "+f"(d[1]), "+f"(d[2]), "+f"(d[3])
        : "r"(a[0]), "r"(a[1]), "r"(a[2]), "r"(a[3]), "r"(b[0]), "r"(b[1]));
}

// ---------------- wlr + zero: block 0 computes wl/wr; all blocks zero cnt ---
__global__ void wlr_zero_kernel(const float* __restrict__ W1, const float* __restrict__ al1,
                                const float* __restrict__ ar1,
                                const float* __restrict__ W2, const float* __restrict__ al2,
                                const float* __restrict__ ar2) {
    int i = blockIdx.x * blockDim.x + threadIdx.x;
    if (i < NN) g_cnt[i] = 0;
    if (blockIdx.x == 0 && threadIdx.x < HIDD) {
        int k = threadIdx.x;
        float l1 = 0.f, r1 = 0.f, l2 = 0.f, r2 = 0.f;
#pragma unroll 4
        for (int n = 0; n < HIDD; n++) {
            float w1 = W1[k * HIDD + n], w2 = W2[k * HIDD + n];
            l1 = fmaf(w1, al1[n], l1); r1 = fmaf(w1, ar1[n], r1);
            l2 = fmaf(w2, al2[n], l2); r2 = fmaf(w2, ar2[n], r2);
        }
        g_wl1[k] = l1; g_wr1[k] = r1; g_wl2[k] = l2; g_wr2[k] = r2;
    }
}

// ---------------- prep: split X; L1/R1; W^T splits; csr count + ordinal -----
__global__ void prep_kernel(const float* __restrict__ X,
                            const float* __restrict__ W1,
                            const float* __restrict__ W2,
                            const int* __restrict__ ei) {
    int i = blockIdx.x * blockDim.x + threadIdx.x;
    if (i < NN * (HIDD / 4)) {
        int lane = i & 31;
        float4 v = ((const float4*)X)[i];
        __nv_bfloat16 h0 = __float2bfloat16(v.x), h1 = __float2bfloat16(v.y);
        __nv_bfloat16 h2 = __float2bfloat16(v.z), h3 = __float2bfloat16(v.w);
        __nv_bfloat162 hp0 = {h0, h1}, hp1 = {h2, h3};
        __nv_bfloat162 lp0 = {__float2bfloat16(v.x - __bfloat162float(h0)),
                              __float2bfloat16(v.y - __bfloat162float(h1))};
        __nv_bfloat162 lp1 = {__float2bfloat16(v.z - __bfloat162float(h2)),
                              __float2bfloat16(v.w - __bfloat162float(h3))};
        ((__nv_bfloat162*)g_Ahi)[i * 2]     = hp0;
        ((__nv_bfloat162*)g_Ahi)[i * 2 + 1] = hp1;
        ((__nv_bfloat162*)g_Alo)[i * 2]     = lp0;
        ((__nv_bfloat162*)g_Alo)[i * 2 + 1] = lp1;
        // fused L/R for layer 1 (warp == one row)
        float4 wl = *(const float4*)(g_wl1 + lane * 4);
        float4 wr = *(const float4*)(g_wr1 + lane * 4);
        float ls = v.x * wl.x + v.y * wl.y + v.z * wl.z + v.w * wl.w;
        float rs = v.x * wr.x + v.y * wr.y + v.z * wr.z + v.w * wr.w;
#pragma unroll
        for (int o = 16; o; o >>= 1) {
            ls += __shfl_xor_sync(0xFFFFFFFFu, ls, o);
            rs += __shfl_xor_sync(0xFFFFFFFFu, rs, o);
        }
        if (lane == 0) { g_L[i >> 5] = ls; g_R[i >> 5] = rs; }
    }
    if (i < HIDD * HIDD) {
        int k = i >> 7, n = i & 127;
        float w1 = W1[i], w2 = W2[i];
        __nv_bfloat16 h1 = __float2bfloat16(w1), h2 = __float2bfloat16(w2);
        g_Bh1[n * HIDD + k] = h1;
        g_Bl1[n * HIDD + k] = __float2bfloat16(w1 - __bfloat162float(h1));
        g_Bh2[n * HIDD + k] = h2;
        g_Bl2[n * HIDD + k] = __float2bfloat16(w2 - __bfloat162float(h2));
    }
    if (i < EE) g_ord[i] = atomicAdd(&g_cnt[ei[EE + i]], 1);  // count + ordinal
}

// ---------------- warp-MMA GEMM: H = X@W via 3-term bf16 split --------------
#define A_BYTES 10240   // 128 rows * 80B (32 bf16 + 8 pad)
#define B_BYTES 10240

__global__ __launch_bounds__(256) void gemm_mma_kernel(
        const __nv_bfloat16* __restrict__ Bhi, const __nv_bfloat16* __restrict__ Blo,
        float* __restrict__ H) {
    __shared__ __align__(16) __nv_bfloat16 As[2][128][40];
    __shared__ __align__(16) __nv_bfloat16 Bs[2][128][40];
    const int tid  = threadIdx.x;
    const int lane = tid & 31;
    const int wid  = tid >> 5;
    const int wm = (wid & 1) * 64;
    const int wn = (wid >> 1) * 32;
    const int row0 = blockIdx.x * 128;
    const uint32_t smA = smem_u32(&As[0][0][0]);
    const uint32_t smB = smem_u32(&Bs[0][0][0]);

    float acc[4][4][4];
#pragma unroll
    for (int mf = 0; mf < 4; mf++)
#pragma unroll
        for (int nf = 0; nf < 4; nf++)
#pragma unroll
            for (int j = 0; j < 4; j++) acc[mf][nf][j] = 0.f;

    auto prefetch = [&](int c) {
        const int term = c >> 2;
        const int kk = (c & 3) * 32;
        const int buf = c & 1;
        const __nv_bfloat16* Asrc = (term == 1) ? g_Alo : g_Ahi;
        const __nv_bfloat16* Bsrc = (term == 2) ? Blo : Bhi;
#pragma unroll
        for (int j = 0; j < 2; j++) {
            int vidx = tid * 2 + j;
            int row = vidx >> 2, q = vidx & 3;
            int grow = row0 + row;
            int ok = (grow < NN) ? 16 : 0;
            int gsafe = (grow < NN) ? grow : (NN - 1);
            cpa16(smA + buf * A_BYTES + row * 80 + q * 16,
                  Asrc + (size_t)gsafe * HIDD + kk + q * 8, ok);
            cpa16(smB + buf * B_BYTES + row * 80 + q * 16,
                  Bsrc + (size_t)row * HIDD + kk + q * 8, 16);
        }
        CPA_COMMIT();
    };

    prefetch(0);
    for (int c = 0; c < 12; c++) {
        if (c + 1 < 12) { prefetch(c + 1); CPA_WAIT1(); }
        else           { CPA_WAIT0(); }
        __syncthreads();
        const int buf = c & 1;
        uint32_t aAddr = smA + buf * A_BYTES + (wm + (lane & 15)) * 80 + (lane >> 4) * 16;
        uint32_t bAddr = smB + buf * B_BYTES + (wn + (lane & 15)) * 80 + (lane >> 4) * 16;
#pragma unroll
        for (int ks = 0; ks < 2; ks++) {
            uint32_t af[4][4], bfr[4][2], t0[4], t1[4];
#pragma unroll
            for (int mf = 0; mf < 4; mf++)
                ldsm4(af[mf], aAddr + mf * (16 * 80) + ks * 32);
            ldsm4(t0, bAddr + ks * 32);
            ldsm4(t1, bAddr + 16 * 80 + ks * 32);
            bfr[0][0] = t0[0]; bfr[0][1] = t0[2];
            bfr[1][0] = t0[1]; bfr[1][1] = t0[3];
            bfr[2][0] = t1[0]; bfr[2][1] = t1[2];
            bfr[3][0] = t1[1]; bfr[3][1] = t1[3];
#pragma unroll
            for (int mf = 0; mf < 4; mf++)
#pragma unroll
                for (int nf = 0; nf < 4; nf++)
                    mma16816(acc[mf][nf], af[mf], bfr[nf]);
        }
        __syncthreads();
    }

    const int g = lane >> 2, tq = lane & 3;
#pragma unroll
    for (int mf = 0; mf < 4; mf++) {
        int r_ = row0 + wm + mf * 16 + g;
#pragma unroll
        for (int nf = 0; nf < 4; nf++) {
            int cc = wn + nf * 8 + tq * 2;
            if (r_ < NN)
                *(float2*)(H + (size_t)r_ * HIDD + cc) = make_float2(acc[mf][nf][0], acc[mf][nf][1]);
            if (r_ + 8 < NN)
                *(float2*)(H + (size_t)(r_ + 8) * HIDD + cc) = make_float2(acc[mf][nf][2], acc[mf][nf][3]);
        }
    }
}

// ---------------- CSR scan (hierarchical) ------------------------------------
__global__ __launch_bounds__(256) void csr_scan1_kernel() {
    __shared__ int ws[8];
    const int tid = threadIdx.x, lane = tid & 31, wid = tid >> 5;
    const int i = blockIdx.x * 256 + tid;
    int v = (i < NN) ? g_cnt[i] : 0;
    int x = v;
#pragma unroll
    for (int o = 1; o < 32; o <<= 1) {
        int y = __shfl_up_sync(0xFFFFFFFFu, x, o);
        if (lane >= o) x += y;
    }
    if (lane == 31) ws[wid] = x;
    __syncthreads();
    if (tid < 8) {
        int s = ws[tid];
#pragma unroll
        for (int o = 1; o < 8; o <<= 1) {
            int y = __shfl_up_sync(0xFFu, s, o);
            if (tid >= o) s += y;
        }
        ws[tid] = s;
    }
    __syncthreads();
    int pre = (wid > 0 ? ws[wid - 1] : 0);
    if (i < NN) g_start[i] = pre + x - v;
    if (tid == 255) g_bsum[blockIdx.x] = pre + x;
}

__global__ __launch_bounds__(256) void csr_scan2_kernel() {
    __shared__ int ws[8];
    const int tid = threadIdx.x, lane = tid & 31, wid = tid >> 5;
    int v = (tid < NB) ? g_bsum[tid] : 0;
    int x = v;
#pragma unroll
    for (int o = 1; o < 32; o <<= 1) {
        int y = __shfl_up_sync(0xFFFFFFFFu, x, o);
        if (lane >= o) x += y;
    }
    if (lane == 31) ws[wid] = x;
    __syncthreads();
    if (tid < 8) {
        int s = ws[tid];
#pragma unroll
        for (int o = 1; o < 8; o <<= 1) {
            int y = __shfl_up_sync(0xFFu, s, o);
            if (tid >= o) s += y;
        }
        ws[tid] = s;
    }
    __syncthreads();
    int pre = (wid > 0 ? ws[wid - 1] : 0);
    if (tid < NB) g_bsum[tid] = pre + x - v;
}

__global__ void csr_scan3_kernel() {
    int i = blockIdx.x * blockDim.x + threadIdx.x;
    if (i < NN) g_start[i] += g_bsum[i >> 8];
    if (i == 0) g_start[NN] = EE;
}

// scatter using precomputed ordinal: no second atomic
__global__ void csr_scatter_kernel(const int* __restrict__ ei) {
    int e = blockIdx.x * blockDim.x + threadIdx.x;
    if (e >= EE) return;
    int s = ei[e], d = ei[EE + e];
    g_csrc[g_start[d] + g_ord[e]] = s;
}

// ============ fused attention mainloop (cp.async smem-staged pipeline) ======
#define ATTN_BODY(LARR)                                                        \
    float4 hd = ((const float4*)(H + (size_t)n * HIDD))[lane];                 \
    float dp = hd.x * hd.x + hd.y * hd.y + hd.z * hd.z + hd.w * hd.w;          \
    _Pragma("unroll")                                                          \
    for (int o = 16; o; o >>= 1) dp += __shfl_xor_sync(0xFFFFFFFFu, dp, o);    \
    float a0 = (Ln + Rd) * __frcp_rn(1.f + __expf(-dp));                       \
    float w0 = __expf(a0);                                                     \
    float den = w0;                                                            \
    float4 acc = make_float4(w0 * hd.x, w0 * hd.y, w0 * hd.z, w0 * hd.w);      \
    const int beg = g_start[n], end = g_start[n + 1];                          \
    float Lst[2][4];                                                           \
    int p = beg, nextp = beg, inflight = 0;                                    \
    if (nextp < end) {                                                         \
        int nb = end - nextp; if (nb > 4) nb = 4;                              \
        _Pragma("unroll")                                                      \
        for (int j = 0; j < 4; j++) {                                          \
            int s = g_csrc[nextp + (j < nb ? j : 0)];                          \
            Lst[0][j] = LARR[s];                                               \
            cpa16(smem_u32(&buf[0][j][lane]),                                  \
                  H + (size_t)s * HIDD + lane * 4, 16);                        \
        }                                                                      \
        CPA_COMMIT(); nextp += 4; inflight = 1;                                \
    }                                                                          \
    if (nextp < end) {                                                         \
        int nb = end - nextp; if (nb > 4) nb = 4;                              \
        _Pragma("unroll")                                                      \
        for (int j = 0; j < 4; j++) {                                          \
            int s = g_csrc[nextp + (j < nb ? j : 0)];                          \
            Lst[1][j] = LARR[s];                                               \
            cpa16(smem_u32(&buf[1][j][lane]),                                  \
                  H + (size_t)s * HIDD + lane * 4, 16);                        \
        }                                                                      \
        CPA_COMMIT(); nextp += 4; inflight = 2;                                \
    }                                                                          \
    int it = 0;                                                                \
    while (p < end) {                                                          \
        if (inflight == 2) { CPA_WAIT1(); } else { CPA_WAIT0(); }              \
        const int st = it & 1;                                                 \
        int nb = end - p; if (nb > 4) nb = 4;                                  \
        float4 cs[4]; float cL[4];                                             \
        _Pragma("unroll")                                                      \
        for (int j = 0; j < 4; j++) { cs[j] = buf[st][j][lane]; cL[j] = Lst[st][j]; } \
        inflight--;                                                            \
        if (nextp < end) {                                                     \
            int nb2 = end - nextp; if (nb2 > 4) nb2 = 4;                       \
            _Pragma("unroll")                                                  \
            for (int j = 0; j < 4; j++) {                                      \
                int s = g_csrc[nextp + (j < nb2 ? j : 0)];                     \
                Lst[st][j] = LARR[s];                                          \
                cpa16(smem_u32(&buf[st][j][lane]),                             \
                      H + (size_t)s * HIDD + lane * 4, 16);                    \
            }                                                                  \
            CPA_COMMIT(); nextp += 4; inflight++;                              \
        }                                                                      \
        float d4[4];                                                           \
        _Pragma("unroll")                                                      \
        for (int j = 0; j < 4; j++)                                            \
            d4[j] = cs[j].x * hd.x + cs[j].y * hd.y + cs[j].z * hd.z + cs[j].w * hd.w; \
        _Pragma("unroll")                                                      \
        for (int o = 16; o; o >>= 1)                                           \
            _Pragma("unroll")                                                  \
            for (int j = 0; j < 4; j++)                                        \
                d4[j] += __shfl_xor_sync(0xFFFFFFFFu, d4[j], o);               \
        _Pragma("unroll")                                                      \
        for (int j = 0; j < 4; j++) {                                          \
            if (j < nb) {                                                      \
                float a = (cL[j] + Rd) * __frcp_rn(1.f + __expf(-d4[j]));      \
                float w = __expf(a);                                           \
                den += w;                                                      \
                acc.x = fmaf(w, cs[j].x, acc.x);                               \
                acc.y = fmaf(w, cs[j].y, acc.y);                               \
                acc.z = fmaf(w, cs[j].z, acc.z);                               \
                acc.w = fmaf(w, cs[j].w, acc.w);                               \
            }                                                                  \
        }                                                                      \
        p += 4; it++;                                                          \
    }

// ---------------- fused attention (layer 2) ---------------------------------
__global__ __launch_bounds__(256) void attn_kernel(
        const float* __restrict__ H, const float* __restrict__ bias,
        const float* __restrict__ Lv, const float* __restrict__ Rv,
        float* __restrict__ out) {
    __shared__ float4 sbuf[8][2][4][32];   // 32 KB
    const int wib  = threadIdx.x >> 5;
    int n    = (blockIdx.x * blockDim.x + threadIdx.x) >> 5;
    int lane = threadIdx.x & 31;
    if (n >= NN) return;
    float4 (*buf)[4][32] = sbuf[wib];
    float Rd = Rv[n];
    float Ln = Lv[n];

    ATTN_BODY(Lv)

    float inv = 1.f / (den + 1e-16f);
    float4 b = ((const float4*)bias)[lane];
    float4 r;
    r.x = fmaf(acc.x, inv, b.x);
    r.y = fmaf(acc.y, inv, b.y);
    r.z = fmaf(acc.z, inv, b.z);
    r.w = fmaf(acc.w, inv, b.w);
    ((float4*)(out + (size_t)n * HIDD))[lane] = r;
}

// ---------------- fused attention (layer 1): epilogue writes bf16 split ----
__global__ __launch_bounds__(256) void attn_split_kernel(
        const float* __restrict__ H, const float* __restrict__ bias) {
    __shared__ float4 sbuf[8][2][4][32];   // 32 KB
    const int wib  = threadIdx.x >> 5;
    int n    = (blockIdx.x * blockDim.x + threadIdx.x) >> 5;
    int lane = threadIdx.x & 31;
    if (n >= NN) return;
    float4 (*buf)[4][32] = sbuf[wib];
    float Rd = g_R[n];
    float Ln = g_L[n];

    ATTN_BODY(g_L)

    float inv = 1.f / (den + 1e-16f);
    float4 b = ((const float4*)bias)[lane];
    float r0 = fmaxf(fmaf(acc.x, inv, b.x), 0.f);
    float r1 = fmaxf(fmaf(acc.y, inv, b.y), 0.f);
    float r2 = fmaxf(fmaf(acc.z, inv, b.z), 0.f);
    float r3 = fmaxf(fmaf(acc.w, inv, b.w), 0.f);

    // bf16 split write (replaces hB write + conv_x kernel)
    __nv_bfloat16 h0 = __float2bfloat16(r0), h1 = __float2bfloat16(r1);
    __nv_bfloat16 h2 = __float2bfloat16(r2), h3 = __float2bfloat16(r3);
    __nv_bfloat162 hp0 = {h0, h1}, hp1 = {h2, h3};
    __nv_bfloat162 lp0 = {__float2bfloat16(r0 - __bfloat162float(h0)),
                          __float2bfloat16(r1 - __bfloat162float(h1))};
    __nv_bfloat162 lp1 = {__float2bfloat16(r2 - __bfloat162float(h2)),
                          __float2bfloat16(r3 - __bfloat162float(h3))};
    ((__nv_bfloat162*)(g_Ahi + (size_t)n * HIDD))[lane * 2]     = hp0;
    ((__nv_bfloat162*)(g_Ahi + (size_t)n * HIDD))[lane * 2 + 1] = hp1;
    ((__nv_bfloat162*)(g_Alo + (size_t)n * HIDD))[lane * 2]     = lp0;
    ((__nv_bfloat162*)(g_Alo + (size_t)n * HIDD))[lane * 2 + 1] = lp1;

    // fused L2/R2 = h . (wl2, wr2) -> SEPARATE buffers (no race with g_L/g_R)
    float4 wl = *(const float4*)(g_wl2 + lane * 4);
    float4 wr = *(const float4*)(g_wr2 + lane * 4);
    float ls = r0 * wl.x + r1 * wl.y + r2 * wl.z + r3 * wl.w;
    float rs = r0 * wr.x + r1 * wr.y + r2 * wr.z + r3 * wr.w;
#pragma unroll
    for (int o = 16; o; o >>= 1) {
        ls += __shfl_xor_sync(0xFFFFFFFFu, ls, o);
        rs += __shfl_xor_sync(0xFFFFFFFFu, rs, o);
    }
    if (lane == 0) { g_L2[n] = ls; g_R2[n] = rs; }
}

// ---------------- classifier decomposition ----------------------------------
__global__ void node_pq_kernel(const float* __restrict__ H,
                               const float* __restrict__ Wc) {
    int lane  = threadIdx.x & 31;
    int warp  = (blockIdx.x * blockDim.x + threadIdx.x) >> 5;
    int nwarp = (gridDim.x * blockDim.x) >> 5;
    float wt[4][4], wb[4][4];
#pragma unroll
    for (int i = 0; i < 4; i++)
#pragma unroll
        for (int o = 0; o < 4; o++) {
            wt[i][o] = Wc[(lane * 4 + i) * OUTD + o];
            wb[i][o] = Wc[(HIDD + lane * 4 + i) * OUTD + o];
        }
    for (int n = warp; n < NN; n += nwarp) {
        float4 hv = ((const float4*)(H + (size_t)n * HIDD))[lane];
        float h4[4] = {hv.x, hv.y, hv.z, hv.w};
        float pv[4] = {0.f, 0.f, 0.f, 0.f}, qv[4] = {0.f, 0.f, 0.f, 0.f};
#pragma unroll
        for (int i = 0; i < 4; i++)
#pragma unroll
            for (int o = 0; o < 4; o++) {
                pv[o] = fmaf(h4[i], wt[i][o], pv[o]);
                qv[o] = fmaf(h4[i], wb[i][o], qv[o]);
            }
#pragma unroll
        for (int o = 0; o < 4; o++)
#pragma unroll
            for (int off = 16; off; off >>= 1) {
                pv[o] += __shfl_xor_sync(0xFFFFFFFFu, pv[o], off);
                qv[o] += __shfl_xor_sync(0xFFFFFFFFu, qv[o], off);
            }
        if (lane == 0) {
            *(float4*)(g_P + (size_t)n * OUTD) = make_float4(pv[0], pv[1], pv[2], pv[3]);
            *(float4*)(g_Q + (size_t)n * OUTD) = make_float4(qv[0], qv[1], qv[2], qv[3]);
        }
    }
}

__global__ void edge_out_kernel(const int* __restrict__ ei,
                                const float* __restrict__ bc,
                                float* __restrict__ out) {
    int e = blockIdx.x * blockDim.x + threadIdx.x;
    if (e >= EE) return;
    int r = ei[e], c = ei[EE + e];
    float4 p = *(const float4*)(g_P + (size_t)r * OUTD);
    float4 q = *(const float4*)(g_Q + (size_t)c * OUTD);
    float b0 = bc[0], b1 = bc[1], b2 = bc[2], b3 = bc[3];
    *(float4*)(out + (size_t)e * OUTD) =
        make_float4(p.x + q.x + b0, p.y + q.y + b1, p.z + q.z + b2, p.w + q.w + b3);
}

// ---------------- launcher ---------------------------------------------------
extern "C" void kernel_launch(void* const* d_in, const int* in_sizes, int n_in,
                              void* d_out, int out_size) {
    const float* x   = (const float*)d_in[0];
    const int*   ei  = (const int*)d_in[1];
    const float* W1  = (const float*)d_in[2];
    const float* al1 = (const float*)d_in[3];
    const float* ar1 = (const float*)d_in[4];
    const float* b1  = (const float*)d_in[5];
    const float* W2  = (const float*)d_in[6];
    const float* al2 = (const float*)d_in[7];
    const float* ar2 = (const float*)d_in[8];
    const float* b2  = (const float*)d_in[9];
    const float* Wc  = (const float*)d_in[10];
    const float* bc  = (const float*)d_in[11];
    float* out = (float*)d_out;

    float *hA, *hB, *L2, *R2;
    __nv_bfloat16 *bh1, *bl1, *bh2, *bl2;
    cudaGetSymbolAddress((void**)&hA, g_hA);
    cudaGetSymbolAddress((void**)&hB, g_hB);
    cudaGetSymbolAddress((void**)&L2, g_L2);
    cudaGetSymbolAddress((void**)&R2, g_R2);
    cudaGetSymbolAddress((void**)&bh1, g_Bh1);
    cudaGetSymbolAddress((void**)&bl1, g_Bl1);
    cudaGetSymbolAddress((void**)&bh2, g_Bh2);
    cudaGetSymbolAddress((void**)&bl2, g_Bl2);

    // one-time host objects (not device memory; legal under alloc guards)
    static cudaStream_t s2 = nullptr;
    static cudaEvent_t evFork = nullptr, evJoin = nullptr;
    if (s2 == nullptr) {
        cudaStreamCreateWithFlags(&s2, cudaStreamNonBlocking);
        cudaEventCreateWithFlags(&evFork, cudaEventDisableTiming);
        cudaEventCreateWithFlags(&evJoin, cudaEventDisableTiming);
    }

    const int TB = 256;
    const int gGemm = (NN + 127) / 128;               // 391
    const int gEdge = (EE + TB - 1) / TB;             // 3125
    const int gAttn = (NN * 32 + TB - 1) / TB;        // 6250
    const int gConv = (NN * 32 + TB - 1) / TB;        // 6250

    // prep: zero+wlr, then split/L/R/W^T/count+ordinal
    wlr_zero_kernel<<<NB, 256>>>(W1, al1, ar1, W2, al2, ar2);
    prep_kernel<<<gConv, TB>>>(x, W1, W2, ei);

    // fork: CSR chain on s2, GEMM-1 on main stream (independent)
    cudaEventRecord(evFork, 0);
    cudaStreamWaitEvent(s2, evFork, 0);
    csr_scan1_kernel<<<NB, 256, 0, s2>>>();
    csr_scan2_kernel<<<1, 256, 0, s2>>>();
    csr_scan3_kernel<<<NB, 256, 0, s2>>>();
    csr_scatter_kernel<<<gEdge, TB, 0, s2>>>(ei);
    cudaEventRecord(evJoin, s2);

    gemm_mma_kernel<<<gGemm, TB>>>(bh1, bl1, hA);     // overlaps CSR chain

    // join: attn needs both gemm1 (program order) and scatter (event)
    cudaStreamWaitEvent(0, evJoin, 0);

    // ---- layer 1 (attn writes bf16 split + L2/R2 to separate buffers) ----
    attn_split_kernel<<<gAttn, TB>>>(hA, b1);

    // ---- layer 2 ----
    gemm_mma_kernel<<<gGemm, TB>>>(bh2, bl2, hA);
    attn_kernel<<<gAttn, TB>>>(hA, b2, L2, R2, hB);

    // ---- edge classifier ----
    node_pq_kernel<<<1184, TB>>>(hB, Wc);
    edge_out_kernel<<<gEdge, TB>>>(ei, bc, out);
}